// round 14
// baseline (speedup 1.0000x reference)
#include <cuda_runtime.h>
#include <cuda_bf16.h>
#include <cstdint>

// ============================================================================
// MultiHeadAttention, reassociated weights + pre-split bf16 cp.async GEMM.
// B=8, S=1024, D=512, H=8, DH=1024.
//
// Round 14: BK=64 stage with 128B rows and 8-way XOR swizzle
// (phys_chunk = chunk ^ (row&7)) -> removes the 2-way smem bank conflicts
// that the 64B-row layout had on EVERY ldmatrix and cp.async store
// (rows r and r+4 aliased mod 128B). Also halves syncthreads count and
// reverts to occ-1 (occ=2 measured neutral). MMA math unchanged.
// ============================================================================

#define LDSM_X4(r0, r1, r2, r3, addr) \
    asm volatile("ldmatrix.sync.aligned.m8n8.x4.shared.b16 {%0,%1,%2,%3}, [%4];" \
                 : "=r"(r0), "=r"(r1), "=r"(r2), "=r"(r3) : "r"(addr))

#define MMA_BF16(d, a, b0, b1) \
    asm volatile("mma.sync.aligned.m16n8k16.row.col.f32.bf16.bf16.f32 " \
                 "{%0,%1,%2,%3}, {%4,%5,%6,%7}, {%8,%9}, {%0,%1,%2,%3};" \
                 : "+f"((d)[0]), "+f"((d)[1]), "+f"((d)[2]), "+f"((d)[3]) \
                 : "r"((a)[0]), "r"((a)[1]), "r"((a)[2]), "r"((a)[3]), \
                   "r"(b0), "r"(b1))

#define CP_ASYNC16(saddr, gptr) \
    asm volatile("cp.async.cg.shared.global [%0], [%1], 16;" \
                 :: "r"(saddr), "l"(gptr) : "memory")
#define CP_COMMIT() asm volatile("cp.async.commit_group;" ::: "memory")
#define CP_WAIT1()  asm volatile("cp.async.wait_group 1;" ::: "memory")
#define CP_WAIT0()  asm volatile("cp.async.wait_group 0;" ::: "memory")

__device__ __forceinline__ uint32_t smem_u32(const void* p) {
    uint32_t a;
    asm("{ .reg .u64 t; cvta.to.shared.u64 t, %1; cvt.u32.u64 %0, t; }"
        : "=r"(a) : "l"(p));
    return a;
}
__device__ __forceinline__ uint32_t pack_hi(float x, float y) {
    uint32_t r;
    asm("prmt.b32 %0, %1, %2, 0x7632;"
        : "=r"(r) : "r"(__float_as_uint(x)), "r"(__float_as_uint(y)));
    return r;
}
__device__ __forceinline__ uint32_t pack_rn(float x, float y) {
    uint32_t r;
    asm("cvt.rn.bf16x2.f32 %0, %1, %2;" : "=r"(r) : "f"(y), "f"(x));
    return r;
}
__device__ __forceinline__ unsigned short bf16_rn(float x) {
    unsigned short r;
    asm("cvt.rn.bf16.f32 %0, %1;" : "=h"(r) : "f"(x));
    return r;
}

// ---------------- device scratch ----------------
__device__ __align__(256) unsigned short g_wkh[(size_t)512 * 8192],  g_wkl[(size_t)512 * 8192];
__device__ __align__(256) unsigned short g_wqh[(size_t)512 * 8192],  g_wql[(size_t)512 * 8192];
__device__ __align__(256) unsigned short g_wvh[(size_t)512 * 8192],  g_wvl[(size_t)512 * 8192];
__device__ __align__(256) unsigned short g_qh [(size_t)8192 * 512],  g_ql [(size_t)8192 * 512];
__device__ __align__(256) unsigned short g_kh [(size_t)8192 * 512],  g_kl [(size_t)8192 * 512];
__device__ __align__(256) unsigned short g_woth[(size_t)512 * 8192], g_wotl[(size_t)512 * 8192];
__device__ __align__(256) unsigned short g_vth[(size_t)8 * 512 * 1024], g_vtl[(size_t)8 * 512 * 1024];
__device__ __align__(256) unsigned short g_mth[(size_t)8 * 512 * 512],  g_mtl[(size_t)8 * 512 * 512];
__device__ __align__(256) unsigned short g_qmh[(size_t)8 * 8192 * 512], g_qml[(size_t)8 * 8192 * 512];
__device__ __align__(256) unsigned short g_ah [(size_t)64 * 1024 * 1024], g_al [(size_t)64 * 1024 * 1024];
__device__ __align__(256) unsigned short g_cvh[(size_t)8192 * 4096], g_cvl[(size_t)8192 * 4096];
__device__ __align__(256) unsigned short g_nth[(size_t)512 * 4096],  g_ntl[(size_t)512 * 4096];
__device__ __align__(256) float g_s   [(size_t)64 * 1024 * 1024];
__device__ __align__(256) float g_o   [(size_t)8192 * 512];
__device__ __align__(256) float g_vv  [8 * 8192];
__device__ __align__(256) float g_w2  [8 * 512];
__device__ __align__(256) float g_cpart[128 * 512];
__device__ __align__(256) float g_crow[512];
__device__ int g_mask_mode;

// ---------------- mask dtype detection ----------------
__global__ void detect_mask_kernel(const unsigned int* __restrict__ m) {
    __shared__ int sawFloat, sawByte;
    if (threadIdx.x == 0) { sawFloat = 0; sawByte = 0; }
    __syncthreads();
    for (int i = threadIdx.x; i < 4096; i += 256) {
        unsigned int w = m[i];
        if (w == 0x3F800000u) sawFloat = 1;
        else if (w > 1u) sawByte = 1;
    }
    __syncthreads();
    if (threadIdx.x == 0) g_mask_mode = sawFloat ? 2 : (sawByte ? 0 : 1);
}

// ---------------- fp32 -> (hi,lo) bf16 split, elementwise ----------------
__global__ void __launch_bounds__(256)
split_kernel(const float* __restrict__ in, unsigned short* __restrict__ hi,
             unsigned short* __restrict__ lo, long n4) {
    long i = (long)blockIdx.x * 256 + threadIdx.x;
    const long stride = (long)gridDim.x * 256;
    for (; i < n4; i += stride) {
        float4 x = ((const float4*)in)[i];
        float t0 = __uint_as_float(__float_as_uint(x.x) & 0xFFFF0000u);
        float t1 = __uint_as_float(__float_as_uint(x.y) & 0xFFFF0000u);
        float t2 = __uint_as_float(__float_as_uint(x.z) & 0xFFFF0000u);
        float t3 = __uint_as_float(__float_as_uint(x.w) & 0xFFFF0000u);
        uint2 hp = { pack_hi(x.x, x.y), pack_hi(x.z, x.w) };
        uint2 lp = { pack_rn(x.x - t0, x.y - t1), pack_rn(x.z - t2, x.w - t3) };
        ((uint2*)hi)[i] = hp;
        ((uint2*)lo)[i] = lp;
    }
}

// ---------------- transpose [R,C] -> [C,R] with split output ----------------
__global__ void __launch_bounds__(256)
transpose_split_kernel(const float* __restrict__ in,
                       unsigned short* __restrict__ hi,
                       unsigned short* __restrict__ lo,
                       int R, int C, long inO, long outO) {
    in += (long)blockIdx.z * inO;
    hi += (long)blockIdx.z * outO;
    lo += (long)blockIdx.z * outO;
    __shared__ float t[32][33];
    int x = blockIdx.x * 32 + threadIdx.x;
    int y0 = blockIdx.y * 32;
#pragma unroll
    for (int j = threadIdx.y; j < 32; j += 8)
        t[j][threadIdx.x] = in[(long)(y0 + j) * C + x];
    __syncthreads();
    int xo = blockIdx.y * 32 + threadIdx.x;
    int yo0 = blockIdx.x * 32;
#pragma unroll
    for (int j = threadIdx.y; j < 32; j += 8) {
        float v = t[threadIdx.x][j];
        uint32_t u = __float_as_uint(v);
        long idx = (long)(yo0 + j) * R + xo;
        hi[idx] = (unsigned short)(u >> 16);
        lo[idx] = bf16_rn(v - __uint_as_float(u & 0xFFFF0000u));
    }
}

// ---------------- bias helper kernels ----------------
__global__ void __launch_bounds__(256)
w2_kernel(const float* __restrict__ Wk, const float* __restrict__ bq,
          float* __restrict__ w2) {
    const int p = blockIdx.x, h = blockIdx.y;
    const int tid = threadIdx.x;
    const float4 a = *(const float4*)(Wk + (long)p * 8192 + h * 1024 + tid * 4);
    const float4 b = *(const float4*)(bq + h * 1024 + tid * 4);
    float s = a.x * b.x + a.y * b.y + a.z * b.z + a.w * b.w;
    __shared__ float red[256];
    red[tid] = s; __syncthreads();
    for (int st = 128; st > 0; st >>= 1) {
        if (tid < st) red[tid] += red[tid + st];
        __syncthreads();
    }
    if (tid == 0) w2[h * 512 + p] = red[0];
}
__global__ void __launch_bounds__(256)
vv_kernel(const float* __restrict__ K, const float* __restrict__ w2,
          float* __restrict__ vv, float scale) {
    const int j = blockIdx.x;
    const int tid = threadIdx.x;
    const int wid = tid >> 5, lane = tid & 31;
    __shared__ float kr[512];
    for (int i = tid; i < 512; i += 256) kr[i] = K[(long)j * 512 + i];
    __syncthreads();
    const float* wr = w2 + wid * 512;
    float s = 0.f;
    for (int p = lane; p < 512; p += 32) s += kr[p] * wr[p];
#pragma unroll
    for (int o = 16; o > 0; o >>= 1) s += __shfl_down_sync(0xFFFFFFFFu, s, o);
    if (lane == 0) vv[wid * 8192 + j] = s * scale;
}
__global__ void __launch_bounds__(256)
crowA_kernel(const float* __restrict__ Wo, const float* __restrict__ bvv,
             float* __restrict__ cpart) {
    const int m0 = blockIdx.x * 64;
    const int tid = threadIdx.x;
    __shared__ float bvs[64];
    if (tid < 64) bvs[tid] = bvv[m0 + tid];
    __syncthreads();
    float s0 = 0.f, s1 = 0.f;
    for (int m = 0; m < 64; m++) {
        const float b = bvs[m];
        const float* row = Wo + (long)(m0 + m) * 512;
        s0 += b * row[tid];
        s1 += b * row[tid + 256];
    }
    cpart[blockIdx.x * 512 + tid] = s0;
    cpart[blockIdx.x * 512 + tid + 256] = s1;
}
__global__ void crowB_kernel(const float* __restrict__ cpart,
                             const float* __restrict__ bo, float* __restrict__ crow) {
    const int o = threadIdx.x;
    float s = bo[o];
    for (int b = 0; b < 128; b++) s += cpart[b * 512 + o];
    crow[o] = s;
}

// ============================================================================
// Pre-split bf16 GEMM: C = A @ B^T; A,B hi/lo bf16 K-major.
// 128x128 tile, BK=64, 256 threads (8 warps of 64x32), cp.async double buffer.
// SMEM stage (64KB): 4 arrays of [128 rows x 128B]; chunk swizzle c^(row&7)
// -> conflict-free ldmatrix + cp.async stores.
// Output: fp32 C (+bias +res) when Ch==nullptr, else split bf16 (Ch,Cl).
// ============================================================================
#define OFF_A_HI 0
#define OFF_A_LO 16384
#define OFF_B_HI 32768
#define OFF_B_LO 49152
#define STAGE 65536
#define GEMM_SMEM (2 * STAGE)

__global__ void __launch_bounds__(256)
tc_gemm2(const unsigned short* __restrict__ Ah, const unsigned short* __restrict__ Al,
         const unsigned short* __restrict__ Bh, const unsigned short* __restrict__ Bl,
         const float* __restrict__ bias, const float* __restrict__ res,
         float* __restrict__ C, unsigned short* __restrict__ Ch,
         unsigned short* __restrict__ Cl,
         int K, int lda, int ldb, int ldc,
         long aO1, long aO2, long bO1, long bO2, long cO1, long cO2, int HD)
{
    extern __shared__ char smem[];
    const uint32_t sb = smem_u32(smem);
    const int tid = threadIdx.x;
    const int wid = tid >> 5;
    const int lane = tid & 31;

    const int z = blockIdx.z;
    const int zb = z / HD, zh = z % HD;
    const long aOff = (long)zb * aO1 + (long)zh * aO2;
    const long bOff = (long)zb * bO1 + (long)zh * bO2;
    const long cOff = (long)zb * cO1 + (long)zh * cO2;

    const int row0 = blockIdx.y * 128;
    const int col0 = blockIdx.x * 128;

    const int wr = wid >> 2;
    const int wc = wid & 3;
    const int wm = wr * 64;
    const int wn = wc * 32;

    // ---- cp.async loader map: thread t -> row t>>1, chunks (t&1)*4 .. +3 ----
    const int lrow = tid >> 1;                 // 0..127
    const int c0 = (tid & 1) * 4;              // chunk base 0 or 4
    const uint32_t srow = (uint32_t)lrow * 128;
    uint32_t sw[4];
#pragma unroll
    for (int j = 0; j < 4; j++)
        sw[j] = (uint32_t)(((c0 + j) ^ (lrow & 7)) << 4);
    const unsigned short* gAh = Ah + aOff + (long)(row0 + lrow) * lda + c0 * 8;
    const unsigned short* gAl = Al + aOff + (long)(row0 + lrow) * lda + c0 * 8;
    const unsigned short* gBh = Bh + bOff + (long)(col0 + lrow) * ldb + c0 * 8;
    const unsigned short* gBl = Bl + bOff + (long)(col0 + lrow) * ldb + c0 * 8;

    // ---- ldmatrix per-thread address components ----
    const int a_rowoff = ((lane >> 3) & 1) * 8 + (lane & 7);
    const int a_ksel = lane >> 4;
    const int a_swz = a_rowoff & 7;
    const int b_rowoff = (lane >> 4) * 8 + (lane & 7);
    const int b_ksel = (lane >> 3) & 1;
    const int b_swz = b_rowoff & 7;

    float acc[4][4][4];
#pragma unroll
    for (int mi = 0; mi < 4; mi++)
#pragma unroll
        for (int ni = 0; ni < 4; ni++)
#pragma unroll
            for (int e = 0; e < 4; e++) acc[mi][ni][e] = 0.f;

    const int nch = K >> 6;                    // BK=64 chunks

    // prologue: chunk 0 -> buffer 0
    {
        const uint32_t st = sb;
#pragma unroll
        for (int j = 0; j < 4; j++) {
            CP_ASYNC16(st + OFF_A_HI + srow + sw[j], gAh + j * 8);
            CP_ASYNC16(st + OFF_A_LO + srow + sw[j], gAl + j * 8);
            CP_ASYNC16(st + OFF_B_HI + srow + sw[j], gBh + j * 8);
            CP_ASYNC16(st + OFF_B_LO + srow + sw[j], gBl + j * 8);
        }
        CP_COMMIT();
    }

    for (int ch = 0; ch < nch; ch++) {
        const int buf = ch & 1;
        const uint32_t stb = sb + buf * STAGE;
        const bool more = (ch + 1) < nch;

        if (more) {
            const int kt = (ch + 1) << 6;
            const uint32_t st = sb + (buf ^ 1) * STAGE;
#pragma unroll
            for (int j = 0; j < 4; j++) {
                CP_ASYNC16(st + OFF_A_HI + srow + sw[j], gAh + kt + j * 8);
                CP_ASYNC16(st + OFF_A_LO + srow + sw[j], gAl + kt + j * 8);
                CP_ASYNC16(st + OFF_B_HI + srow + sw[j], gBh + kt + j * 8);
                CP_ASYNC16(st + OFF_B_LO + srow + sw[j], gBl + kt + j * 8);
            }
            CP_COMMIT();
            CP_WAIT1();
        } else {
            CP_WAIT0();
        }
        __syncthreads();

        const uint32_t aBaseHi = stb + OFF_A_HI + (wm + a_rowoff) * 128;
        const uint32_t aBaseLo = stb + OFF_A_LO + (wm + a_rowoff) * 128;
#pragma unroll
        for (int ks = 0; ks < 4; ks++) {
            uint32_t bh[8], bl[8];
            {
                const uint32_t csel = ((uint32_t)((ks * 2 + b_ksel) ^ b_swz)) << 4;
#pragma unroll
                for (int p = 0; p < 2; p++) {
                    const uint32_t ro = (wn + p * 16 + b_rowoff) * 128 + csel;
                    LDSM_X4(bh[p*4+0], bh[p*4+1], bh[p*4+2], bh[p*4+3],
                            stb + OFF_B_HI + ro);
                    LDSM_X4(bl[p*4+0], bl[p*4+1], bl[p*4+2], bl[p*4+3],
                            stb + OFF_B_LO + ro);
                }
            }
            const uint32_t acsel = ((uint32_t)((ks * 2 + a_ksel) ^ a_swz)) << 4;
#pragma unroll
            for (int mi = 0; mi < 4; mi++) {
                uint32_t ah[4], al[4];
                LDSM_X4(ah[0], ah[1], ah[2], ah[3], aBaseHi + mi * 16 * 128 + acsel);
                LDSM_X4(al[0], al[1], al[2], al[3], aBaseLo + mi * 16 * 128 + acsel);
#pragma unroll
                for (int ni = 0; ni < 4; ni++)
                    MMA_BF16(acc[mi][ni], ah, bh[ni*2], bh[ni*2+1]);
#pragma unroll
                for (int ni = 0; ni < 4; ni++)
                    MMA_BF16(acc[mi][ni], ah, bl[ni*2], bl[ni*2+1]);
#pragma unroll
                for (int ni = 0; ni < 4; ni++)
                    MMA_BF16(acc[mi][ni], al, bh[ni*2], bh[ni*2+1]);
            }
        }
        __syncthreads();
    }

    // ---- epilogue ----
    const int erow = lane >> 2;
    const int ecol = (lane & 3) * 2;
#pragma unroll
    for (int mi = 0; mi < 4; mi++) {
        const int r0 = row0 + wm + mi * 16 + erow;
        const int r1 = r0 + 8;
#pragma unroll
        for (int ni = 0; ni < 4; ni++) {
            const int c = col0 + wn + ni * 8 + ecol;
            float v0 = acc[mi][ni][0], v1 = acc[mi][ni][1];
            float v2 = acc[mi][ni][2], v3 = acc[mi][ni][3];
            if (bias) {
                const float b0 = bias[c], b1 = bias[c + 1];
                v0 += b0; v1 += b1; v2 += b0; v3 += b1;
            }
            if (res) {
                float2 q0 = *(const float2*)(res + (long)r0 * ldc + c);
                float2 q1 = *(const float2*)(res + (long)r1 * ldc + c);
                v0 += q0.x; v1 += q0.y; v2 += q1.x; v3 += q1.y;
            }
            if (Ch) {
                float t0 = __uint_as_float(__float_as_uint(v0) & 0xFFFF0000u);
                float t1 = __uint_as_float(__float_as_uint(v1) & 0xFFFF0000u);
                float t2 = __uint_as_float(__float_as_uint(v2) & 0xFFFF0000u);
                float t3 = __uint_as_float(__float_as_uint(v3) & 0xFFFF0000u);
                *(uint32_t*)(Ch + cOff + (long)r0 * ldc + c) = pack_hi(v0, v1);
                *(uint32_t*)(Cl + cOff + (long)r0 * ldc + c) = pack_rn(v0 - t0, v1 - t1);
                *(uint32_t*)(Ch + cOff + (long)r1 * ldc + c) = pack_hi(v2, v3);
                *(uint32_t*)(Cl + cOff + (long)r1 * ldc + c) = pack_rn(v2 - t2, v3 - t3);
            } else {
                float2 o0 = {v0, v1}, o1 = {v2, v3};
                *(float2*)(C + cOff + (long)r0 * ldc + c) = o0;
                *(float2*)(C + cOff + (long)r1 * ldc + c) = o1;
            }
        }
    }
}

// ---------------- softmax: fp32 scores -> split bf16 attn ----------------
__global__ void __launch_bounds__(256)
softmax_kernel(const float* __restrict__ s, const void* __restrict__ mask,
               const float* __restrict__ vv,
               unsigned short* __restrict__ ah, unsigned short* __restrict__ al,
               int S, int H, float scale)
{
    const int i = blockIdx.x;
    const int z = blockIdx.y;
    const int b = z / H;
    const int h = z % H;
    const long base = ((long)z * S + (long)i) * S;
    const float* p = s + base;
    const float* vsp = vv + h * 8192 + b * 1024;
    const long mbase = (long)b * S * S + (long)i * S;
    const int tid = threadIdx.x;
    const int mode = g_mask_mode;

    bool mk[4];
    if (mode == 0) {
        const unsigned char* mp = (const unsigned char*)mask + mbase;
#pragma unroll
        for (int r = 0; r < 4; r++) mk[r] = mp[tid + r * 256] != 0;
    } else if (mode == 1) {
        const int* mp = (const int*)mask + mbase;
#pragma unroll
        for (int r = 0; r < 4; r++) mk[r] = mp[tid + r * 256] != 0;
    } else {
        const float* mp = (const float*)mask + mbase;
#pragma unroll
        for (int r = 0; r < 4; r++) mk[r] = mp[tid + r * 256] != 0.f;
    }

    float v[4];
    float mx = -3.4e38f;
#pragma unroll
    for (int r = 0; r < 4; r++) {
        const int j = tid + r * 256;
        float x = p[j] * scale + vsp[j];
        if (mk[r]) x = -1e9f;
        v[r] = x;
        mx = fmaxf(mx, x);
    }
    __shared__ float red[256];
    red[tid] = mx; __syncthreads();
    for (int st = 128; st > 0; st >>= 1) {
        if (tid < st) red[tid] = fmaxf(red[tid], red[tid + st]);
        __syncthreads();
    }
    mx = red[0]; __syncthreads();
    float sum = 0.f;
#pragma unroll
    for (int r = 0; r < 4; r++) { v[r] = __expf(v[r] - mx); sum += v[r]; }
    red[tid] = sum; __syncthreads();
    for (int st = 128; st > 0; st >>= 1) {
        if (tid < st) red[tid] += red[tid + st];
        __syncthreads();
    }
    const float inv = 1.f / red[0];
#pragma unroll
    for (int r = 0; r < 4; r++) {
        const long idx = base + tid + r * 256;
        const float x = v[r] * inv;
        const uint32_t u = __float_as_uint(x);
        ah[idx] = (unsigned short)(u >> 16);
        al[idx] = bf16_rn(x - __uint_as_float(u & 0xFFFF0000u));
    }
}

// ---------------- LayerNorm over D=512 ----------------
__global__ void __launch_bounds__(256)
layernorm_kernel(const float* __restrict__ x, const float* __restrict__ gamma,
                 const float* __restrict__ beta, float* __restrict__ out, int D)
{
    const int row = blockIdx.x;
    const float* p = x + (long)row * D;
    const int tid = threadIdx.x;
    const float a0 = p[tid];
    const float a1 = p[tid + 256];
    __shared__ float red[256];
    red[tid] = a0 + a1; __syncthreads();
    for (int st = 128; st > 0; st >>= 1) {
        if (tid < st) red[tid] += red[tid + st];
        __syncthreads();
    }
    const float mean = red[0] / (float)D; __syncthreads();
    const float d0 = a0 - mean, d1 = a1 - mean;
    red[tid] = d0 * d0 + d1 * d1; __syncthreads();
    for (int st = 128; st > 0; st >>= 1) {
        if (tid < st) red[tid] += red[tid + st];
        __syncthreads();
    }
    const float rstd = rsqrtf(red[0] / (float)D + 1e-5f);
    out[(long)row * D + tid]       = d0 * rstd * gamma[tid] + beta[tid];
    out[(long)row * D + tid + 256] = d1 * rstd * gamma[tid + 256] + beta[tid + 256];
}

// ---------------- launch ----------------
extern "C" void kernel_launch(void* const* d_in, const int* in_sizes, int n_in,
                              void* d_out, int out_size)
{
    const float* Q     = (const float*)d_in[0];
    const float* Kin   = (const float*)d_in[1];
    const float* Vin   = (const float*)d_in[2];
    const void*  Mask  = d_in[3];
    const float* Wq    = (const float*)d_in[4];
    const float* bq    = (const float*)d_in[5];
    const float* Wk    = (const float*)d_in[6];
    const float* bv    = (const float*)d_in[9];
    const float* Wv    = (const float*)d_in[8];
    const float* Wo    = (const float*)d_in[10];
    const float* bo    = (const float*)d_in[11];
    const float* gamma = (const float*)d_in[12];
    const float* beta  = (const float*)d_in[13];
    float* out = (float*)d_out;

    unsigned short *wkh,*wkl,*wqh,*wql,*wvh,*wvl,*qh,*ql,*kh,*kl;
    unsigned short *woth,*wotl,*vth,*vtl,*mth,*mtl,*qmh,*qml,*ah,*al,*cvh,*cvl,*nth,*ntl;
    float *s,*o,*vv,*w2,*cpart,*crow;
    cudaGetSymbolAddress((void**)&wkh, g_wkh);  cudaGetSymbolAddress((void**)&wkl, g_wkl);
    cudaGetSymbolAddress((void**)&wqh, g_wqh);  cudaGetSymbolAddress((void**)&wql, g_wql);
    cudaGetSymbolAddress((void**)&wvh, g_wvh);  cudaGetSymbolAddress((void**)&wvl, g_wvl);
    cudaGetSymbolAddress((void**)&qh,  g_qh);   cudaGetSymbolAddress((void**)&ql,  g_ql);
    cudaGetSymbolAddress((void**)&kh,  g_kh);   cudaGetSymbolAddress((void**)&kl,  g_kl);
    cudaGetSymbolAddress((void**)&woth,g_woth); cudaGetSymbolAddress((void**)&wotl,g_wotl);
    cudaGetSymbolAddress((void**)&vth, g_vth);  cudaGetSymbolAddress((void**)&vtl, g_vtl);
    cudaGetSymbolAddress((void**)&mth, g_mth);  cudaGetSymbolAddress((void**)&mtl, g_mtl);
    cudaGetSymbolAddress((void**)&qmh, g_qmh);  cudaGetSymbolAddress((void**)&qml, g_qml);
    cudaGetSymbolAddress((void**)&ah,  g_ah);   cudaGetSymbolAddress((void**)&al,  g_al);
    cudaGetSymbolAddress((void**)&cvh, g_cvh);  cudaGetSymbolAddress((void**)&cvl, g_cvl);
    cudaGetSymbolAddress((void**)&nth, g_nth);  cudaGetSymbolAddress((void**)&ntl, g_ntl);
    cudaGetSymbolAddress((void**)&s,   g_s);
    cudaGetSymbolAddress((void**)&o,   g_o);
    cudaGetSymbolAddress((void**)&vv,  g_vv);
    cudaGetSymbolAddress((void**)&w2,  g_w2);
    cudaGetSymbolAddress((void**)&cpart, g_cpart);
    cudaGetSymbolAddress((void**)&crow,  g_crow);

    cudaFuncSetAttribute(tc_gemm2, cudaFuncAttributeMaxDynamicSharedMemorySize, GEMM_SMEM);

    const int S = 1024, H = 8;
    const long SS = (long)S * S;
    const long N4W = (long)512 * 8192 / 4;
    dim3 blk(256);

    // 0-4: mask dtype + splits feeding G1..G3
    detect_mask_kernel<<<1, 256>>>((const unsigned int*)Mask);
    split_kernel<<<1024, blk>>>(Wk,  wkh, wkl, N4W);
    split_kernel<<<1024, blk>>>(Wq,  wqh, wql, N4W);
    split_kernel<<<1024, blk>>>(Q,   qh,  ql,  N4W);
    split_kernel<<<1024, blk>>>(Kin, kh,  kl,  N4W);

    // G1: mt[h][q][p] = sum_d Wk[q,hd] * Wq[p,hd]
    tc_gemm2<<<dim3(4, 4, 8), blk, GEMM_SMEM>>>(wkh, wkl, wqh, wql,
        nullptr, nullptr, nullptr, mth, mtl,
        1024, 8192, 8192, 512,
        0, 1024, 0, 1024, 0, (long)512 * 512, 8);

    // G2: qm[h][i][q] = (Q @ M_h)[i,q]
    tc_gemm2<<<dim3(4, 64, 8), blk, GEMM_SMEM>>>(qh, ql, mth, mtl,
        nullptr, nullptr, nullptr, qmh, qml,
        512, 512, 512, 512,
        0, 0, 0, (long)512 * 512, 0, (long)8192 * 512, 8);

    // G3: s (fp32) = qm @ K^T per (b,h)
    tc_gemm2<<<dim3(8, 8, 64), blk, GEMM_SMEM>>>(qmh, qml, kh, kl,
        nullptr, nullptr, s, nullptr, nullptr,
        512, 512, 512, 1024,
        (long)1024 * 512, (long)8192 * 512,
        (long)1024 * 512, 0,
        (long)H * SS, SS, 8);

    // helpers + remaining splits
    w2_kernel<<<dim3(512, 8), blk>>>(Wk, bq, w2);
    vv_kernel<<<8192, blk>>>(Kin, w2, vv, 0.03125f);
    split_kernel<<<1024, blk>>>(Wv, wvh, wvl, N4W);
    transpose_split_kernel<<<dim3(16, 256, 1), dim3(32, 8)>>>(Wo, woth, wotl,
                                                              8192, 512, 0, 0);
    transpose_split_kernel<<<dim3(16, 32, 8), dim3(32, 8)>>>(Vin, vth, vtl,
                                                             1024, 512, 524288, 524288);

    // softmax: scale + col-bias + mask + softmax -> split bf16 attn
    softmax_kernel<<<dim3(S, 64), blk>>>(s, Mask, vv, ah, al, S, H, 0.03125f);

    // G5: ctxv = attn @ vt^T -> split
    tc_gemm2<<<dim3(4, 8, 64), blk, GEMM_SMEM>>>(ah, al, vth, vtl,
        nullptr, nullptr, nullptr, cvh, cvl,
        1024, 1024, 1024, 4096,
        (long)H * SS, SS,
        (long)512 * 1024, 0,
        (long)1024 * 4096, 512, 8);

    // G6: nt = wot @ Wv^T per h -> split
    tc_gemm2<<<dim3(4, 4, 8), blk, GEMM_SMEM>>>(woth, wotl, wvh, wvl,
        nullptr, nullptr, nullptr, nth, ntl,
        1024, 8192, 8192, 4096,
        0, 1024, 0, 1024, 0, 512, 8);

    // crow (needed only by G7)
    crowA_kernel<<<128, blk>>>(Wo, bv, cpart);
    crowB_kernel<<<1, 512>>>(cpart, bo, crow);

    // G7: o = ctxv @ nt^T + crow + Q  (fp32 out)
    tc_gemm2<<<dim3(4, 64, 1), blk, GEMM_SMEM>>>(cvh, cvl, nth, ntl,
        crow, Q, o, nullptr, nullptr,
        4096, 4096, 4096, 512,
        0, 0, 0, 0, 0, 0, 1);

    // LayerNorm
    layernorm_kernel<<<8192, blk>>>(o, gamma, beta, out, 512);
}

// round 17
// speedup vs baseline: 1.2728x; 1.2728x over previous
#include <cuda_runtime.h>
#include <cuda_fp16.h>
#include <cstdint>

// ============================================================================
// MultiHeadAttention, reassociated weights + fp16 2-product cp.async GEMM.
// B=8, S=1024, D=512, H=8, DH=1024.
//
// Round 17: resubmission of the audited round-15/16 kernel (broker flake is
// content-independent; audited designs get resubmitted until they execute).
// fp16 ASYMMETRIC split: A = Ah + Al (fp16 pair, ~21 bits), B rounded once
// to fp16; C = Ah*Bs + Al*Bs (2 MMAs instead of 3; -33% MMA issue).
// Est. end-to-end rel_err ~2.5e-4 (<1e-3 gate).
// ============================================================================

#define LDSM_X4(r0, r1, r2, r3, addr) \
    asm volatile("ldmatrix.sync.aligned.m8n8.x4.shared.b16 {%0,%1,%2,%3}, [%4];" \
                 : "=r"(r0), "=r"(r1), "=r"(r2), "=r"(r3) : "r"(addr))

#define MMA_FP16(d, a, b0, b1) \
    asm volatile("mma.sync.aligned.m16n8k16.row.col.f32.f16.f16.f32 " \
                 "{%0,%1,%2,%3}, {%4,%5,%6,%7}, {%8,%9}, {%0,%1,%2,%3};" \
                 : "+f"((d)[0]), "+f"((d)[1]), "+f"((d)[2]), "+f"((d)[3]) \
                 : "r"((a)[0]), "r"((a)[1]), "r"((a)[2]), "r"((a)[3]), \
                   "r"(b0), "r"(b1))

#define CP_ASYNC16(saddr, gptr) \
    asm volatile("cp.async.cg.shared.global [%0], [%1], 16;" \
                 :: "r"(saddr), "l"(gptr) : "memory")
#define CP_COMMIT() asm volatile("cp.async.commit_group;" ::: "memory")
#define CP_WAIT1()  asm volatile("cp.async.wait_group 1;" ::: "memory")
#define CP_WAIT0()  asm volatile("cp.async.wait_group 0;" ::: "memory")

__device__ __forceinline__ uint32_t smem_u32(const void* p) {
    uint32_t a;
    asm("{ .reg .u64 t; cvta.to.shared.u64 t, %1; cvt.u32.u64 %0, t; }"
        : "=r"(a) : "l"(p));
    return a;
}
// pack two fp32 -> f16x2 (x in low half, matching memory order)
__device__ __forceinline__ uint32_t pack_h2(float x, float y) {
    uint32_t r;
    asm("cvt.rn.f16x2.f32 %0, %1, %2;" : "=r"(r) : "f"(y), "f"(x));
    return r;
}
__device__ __forceinline__ void split16(float x, __half& h, __half& l) {
    h = __float2half_rn(x);
    l = __float2half_rn(x - __half2float(h));
}

// ---------------- device scratch ----------------
__device__ __align__(256) __half g_wkh[(size_t)512 * 8192],  g_wkl[(size_t)512 * 8192];
__device__ __align__(256) __half g_wqs[(size_t)512 * 8192];
__device__ __align__(256) __half g_qhh[(size_t)8192 * 512],  g_qll[(size_t)8192 * 512];
__device__ __align__(256) __half g_ksg[(size_t)8192 * 512];
__device__ __align__(256) __half g_wvs[(size_t)512 * 8192];
__device__ __align__(256) __half g_woth[(size_t)512 * 8192], g_wotl[(size_t)512 * 8192];
__device__ __align__(256) __half g_vts[(size_t)8 * 512 * 1024];
__device__ __align__(256) __half g_mts[(size_t)8 * 512 * 512];
__device__ __align__(256) __half g_qmh[(size_t)8 * 8192 * 512], g_qml[(size_t)8 * 8192 * 512];
__device__ __align__(256) __half g_ah [(size_t)64 * 1024 * 1024], g_al [(size_t)64 * 1024 * 1024];
__device__ __align__(256) __half g_cvh[(size_t)8192 * 4096], g_cvl[(size_t)8192 * 4096];
__device__ __align__(256) __half g_nts[(size_t)512 * 4096];
__device__ __align__(256) float g_s   [(size_t)64 * 1024 * 1024];
__device__ __align__(256) float g_o   [(size_t)8192 * 512];
__device__ __align__(256) float g_vv  [8 * 8192];
__device__ __align__(256) float g_w2  [8 * 512];
__device__ __align__(256) float g_cpart[128 * 512];
__device__ __align__(256) float g_crow[512];
__device__ int g_mask_mode;

// ---------------- mask dtype detection ----------------
__global__ void detect_mask_kernel(const unsigned int* __restrict__ m) {
    __shared__ int sawFloat, sawByte;
    if (threadIdx.x == 0) { sawFloat = 0; sawByte = 0; }
    __syncthreads();
    for (int i = threadIdx.x; i < 4096; i += 256) {
        unsigned int w = m[i];
        if (w == 0x3F800000u) sawFloat = 1;
        else if (w > 1u) sawByte = 1;
    }
    __syncthreads();
    if (threadIdx.x == 0) g_mask_mode = sawFloat ? 2 : (sawByte ? 0 : 1);
}

// ---------------- fp32 -> fp16 (hi,lo) pair, elementwise ----------------
__global__ void __launch_bounds__(256)
split_pair_kernel(const float* __restrict__ in, __half* __restrict__ hi,
                  __half* __restrict__ lo, long n4) {
    long i = (long)blockIdx.x * 256 + threadIdx.x;
    const long stride = (long)gridDim.x * 256;
    for (; i < n4; i += stride) {
        float4 x = ((const float4*)in)[i];
        __half h0, l0, h1, l1, h2, l2, h3, l3;
        split16(x.x, h0, l0); split16(x.y, h1, l1);
        split16(x.z, h2, l2); split16(x.w, h3, l3);
        uint2 hp = { (uint32_t)(__half_as_ushort(h0) | ((uint32_t)__half_as_ushort(h1) << 16)),
                     (uint32_t)(__half_as_ushort(h2) | ((uint32_t)__half_as_ushort(h3) << 16)) };
        uint2 lp = { (uint32_t)(__half_as_ushort(l0) | ((uint32_t)__half_as_ushort(l1) << 16)),
                     (uint32_t)(__half_as_ushort(l2) | ((uint32_t)__half_as_ushort(l3) << 16)) };
        ((uint2*)hi)[i] = hp;
        ((uint2*)lo)[i] = lp;
    }
}

// ---------------- fp32 -> fp16 single, elementwise ----------------
__global__ void __launch_bounds__(256)
round_kernel(const float* __restrict__ in, __half* __restrict__ out, long n4) {
    long i = (long)blockIdx.x * 256 + threadIdx.x;
    const long stride = (long)gridDim.x * 256;
    for (; i < n4; i += stride) {
        float4 x = ((const float4*)in)[i];
        uint2 p = { pack_h2(x.x, x.y), pack_h2(x.z, x.w) };
        ((uint2*)out)[i] = p;
    }
}

// ---------------- transpose [R,C]->[C,R], fp16 pair output ----------------
__global__ void __launch_bounds__(256)
transpose_pair_kernel(const float* __restrict__ in,
                      __half* __restrict__ hi, __half* __restrict__ lo,
                      int R, int C, long inO, long outO) {
    in += (long)blockIdx.z * inO;
    hi += (long)blockIdx.z * outO;
    lo += (long)blockIdx.z * outO;
    __shared__ float t[32][33];
    int x = blockIdx.x * 32 + threadIdx.x;
    int y0 = blockIdx.y * 32;
#pragma unroll
    for (int j = threadIdx.y; j < 32; j += 8)
        t[j][threadIdx.x] = in[(long)(y0 + j) * C + x];
    __syncthreads();
    int xo = blockIdx.y * 32 + threadIdx.x;
    int yo0 = blockIdx.x * 32;
#pragma unroll
    for (int j = threadIdx.y; j < 32; j += 8) {
        __half h, l;
        split16(t[threadIdx.x][j], h, l);
        long idx = (long)(yo0 + j) * R + xo;
        hi[idx] = h;
        lo[idx] = l;
    }
}
// ---------------- transpose [R,C]->[C,R], fp16 single output ----------------
__global__ void __launch_bounds__(256)
transpose_single_kernel(const float* __restrict__ in, __half* __restrict__ out,
                        int R, int C, long inO, long outO) {
    in += (long)blockIdx.z * inO;
    out += (long)blockIdx.z * outO;
    __shared__ float t[32][33];
    int x = blockIdx.x * 32 + threadIdx.x;
    int y0 = blockIdx.y * 32;
#pragma unroll
    for (int j = threadIdx.y; j < 32; j += 8)
        t[j][threadIdx.x] = in[(long)(y0 + j) * C + x];
    __syncthreads();
    int xo = blockIdx.y * 32 + threadIdx.x;
    int yo0 = blockIdx.x * 32;
#pragma unroll
    for (int j = threadIdx.y; j < 32; j += 8)
        out[(long)(yo0 + j) * R + xo] = __float2half_rn(t[threadIdx.x][j]);
}

// ---------------- bias helper kernels (fp32) ----------------
__global__ void __launch_bounds__(256)
w2_kernel(const float* __restrict__ Wk, const float* __restrict__ bq,
          float* __restrict__ w2) {
    const int p = blockIdx.x, h = blockIdx.y;
    const int tid = threadIdx.x;
    const float4 a = *(const float4*)(Wk + (long)p * 8192 + h * 1024 + tid * 4);
    const float4 b = *(const float4*)(bq + h * 1024 + tid * 4);
    float s = a.x * b.x + a.y * b.y + a.z * b.z + a.w * b.w;
    __shared__ float red[256];
    red[tid] = s; __syncthreads();
    for (int st = 128; st > 0; st >>= 1) {
        if (tid < st) red[tid] += red[tid + st];
        __syncthreads();
    }
    if (tid == 0) w2[h * 512 + p] = red[0];
}
__global__ void __launch_bounds__(256)
vv_kernel(const float* __restrict__ K, const float* __restrict__ w2,
          float* __restrict__ vv, float scale) {
    const int j = blockIdx.x;
    const int tid = threadIdx.x;
    const int wid = tid >> 5, lane = tid & 31;
    __shared__ float kr[512];
    for (int i = tid; i < 512; i += 256) kr[i] = K[(long)j * 512 + i];
    __syncthreads();
    const float* wr = w2 + wid * 512;
    float s = 0.f;
    for (int p = lane; p < 512; p += 32) s += kr[p] * wr[p];
#pragma unroll
    for (int o = 16; o > 0; o >>= 1) s += __shfl_down_sync(0xFFFFFFFFu, s, o);
    if (lane == 0) vv[wid * 8192 + j] = s * scale;
}
__global__ void __launch_bounds__(256)
crowA_kernel(const float* __restrict__ Wo, const float* __restrict__ bvv,
             float* __restrict__ cpart) {
    const int m0 = blockIdx.x * 64;
    const int tid = threadIdx.x;
    __shared__ float bvs[64];
    if (tid < 64) bvs[tid] = bvv[m0 + tid];
    __syncthreads();
    float s0 = 0.f, s1 = 0.f;
    for (int m = 0; m < 64; m++) {
        const float b = bvs[m];
        const float* row = Wo + (long)(m0 + m) * 512;
        s0 += b * row[tid];
        s1 += b * row[tid + 256];
    }
    cpart[blockIdx.x * 512 + tid] = s0;
    cpart[blockIdx.x * 512 + tid + 256] = s1;
}
__global__ void crowB_kernel(const float* __restrict__ cpart,
                             const float* __restrict__ bo, float* __restrict__ crow) {
    const int o = threadIdx.x;
    float s = bo[o];
    for (int b = 0; b < 128; b++) s += cpart[b * 512 + o];
    crow[o] = s;
}

// ============================================================================
// fp16 2-product GEMM: C = A @ B^T; A as (Ah,Al) fp16 pair, B single fp16.
// 128x128 tile, BK=32, 256 threads (8 warps 64x32), cp.async double buffer.
// SMEM stage (24KB): A_hi[128x32], A_lo, B as fp16, 64B rows,
// 16B-chunk XOR swizzle: phys_chunk = chunk ^ (row&3).
// Output: fp32 C (+bias +res) | fp16 pair (Ch,Cl) | fp16 single (Ch only).
// ============================================================================
#define OFF_A_HI 0
#define OFF_A_LO 8192
#define OFF_B    16384
#define STAGE 24576
#define GEMM_SMEM (2 * STAGE)

__global__ void __launch_bounds__(256)
tc_gemm3(const __half* __restrict__ Ah, const __half* __restrict__ Al,
         const __half* __restrict__ Bs,
         const float* __restrict__ bias, const float* __restrict__ res,
         float* __restrict__ C, __half* __restrict__ Ch, __half* __restrict__ Cl,
         int K, int lda, int ldb, int ldc,
         long aO1, long aO2, long bO1, long bO2, long cO1, long cO2, int HD)
{
    extern __shared__ char smem[];
    const uint32_t sb = smem_u32(smem);
    const int tid = threadIdx.x;
    const int wid = tid >> 5;
    const int lane = tid & 31;

    const int z = blockIdx.z;
    const int zb = z / HD, zh = z % HD;
    const long aOff = (long)zb * aO1 + (long)zh * aO2;
    const long bOff = (long)zb * bO1 + (long)zh * bO2;
    const long cOff = (long)zb * cO1 + (long)zh * cO2;

    const int row0 = blockIdx.y * 128;
    const int col0 = blockIdx.x * 128;

    const int wr = wid >> 2;
    const int wc = wid & 3;
    const int wm = wr * 64;
    const int wn = wc * 32;

    // cp.async loader map: thread t -> row t>>1, chunk pair (t&1)*2
    const int lrow = tid >> 1;
    const int c0 = (tid & 1) * 2;
    const uint32_t srow = lrow * 64;
    const uint32_t sw0 = (uint32_t)((c0 ^ (lrow & 3)) << 4);
    const uint32_t sw1 = (uint32_t)(((c0 + 1) ^ (lrow & 3)) << 4);
    const __half* gAh = Ah + aOff + (long)(row0 + lrow) * lda + c0 * 8;
    const __half* gAl = Al + aOff + (long)(row0 + lrow) * lda + c0 * 8;
    const __half* gB  = Bs + bOff + (long)(col0 + lrow) * ldb + c0 * 8;

    const int a_rowoff = ((lane >> 3) & 1) * 8 + (lane & 7);
    const int a_ksel = lane >> 4;
    const int a_swz = a_rowoff & 3;
    const int b_rowoff = (lane >> 4) * 8 + (lane & 7);
    const int b_ksel = (lane >> 3) & 1;
    const int b_swz = b_rowoff & 3;

    float acc[4][4][4];
#pragma unroll
    for (int mi = 0; mi < 4; mi++)
#pragma unroll
        for (int ni = 0; ni < 4; ni++)
#pragma unroll
            for (int e = 0; e < 4; e++) acc[mi][ni][e] = 0.f;

    const int nch = K >> 5;

    // prologue: chunk 0 -> buffer 0
    {
        const uint32_t st = sb;
        CP_ASYNC16(st + OFF_A_HI + srow + sw0, gAh);
        CP_ASYNC16(st + OFF_A_HI + srow + sw1, gAh + 8);
        CP_ASYNC16(st + OFF_A_LO + srow + sw0, gAl);
        CP_ASYNC16(st + OFF_A_LO + srow + sw1, gAl + 8);
        CP_ASYNC16(st + OFF_B    + srow + sw0, gB);
        CP_ASYNC16(st + OFF_B    + srow + sw1, gB + 8);
        CP_COMMIT();
    }

    for (int ch = 0; ch < nch; ch++) {
        const int buf = ch & 1;
        const uint32_t stb = sb + buf * STAGE;
        const bool more = (ch + 1) < nch;

        if (more) {
            const int kt = (ch + 1) << 5;
            const uint32_t st = sb + (buf ^ 1) * STAGE;
            CP_ASYNC16(st + OFF_A_HI + srow + sw0, gAh + kt);
            CP_ASYNC16(st + OFF_A_HI + srow + sw1, gAh + kt + 8);
            CP_ASYNC16(st + OFF_A_LO + srow + sw0, gAl + kt);
            CP_ASYNC16(st + OFF_A_LO + srow + sw1, gAl + kt + 8);
            CP_ASYNC16(st + OFF_B    + srow + sw0, gB + kt);
            CP_ASYNC16(st + OFF_B    + srow + sw1, gB + kt + 8);
            CP_COMMIT();
            CP_WAIT1();
        } else {
            CP_WAIT0();
        }
        __syncthreads();

        const uint32_t aBaseHi = stb + OFF_A_HI + (wm + a_rowoff) * 64;
        const uint32_t aBaseLo = stb + OFF_A_LO + (wm + a_rowoff) * 64;
#pragma unroll
        for (int ks = 0; ks < 2; ks++) {
            uint32_t bh[8];
            {
                const uint32_t csel = ((uint32_t)(ks * 2 + b_ksel) ^ b_swz) << 4;
#pragma unroll
                for (int p = 0; p < 2; p++) {
                    const uint32_t ro = (wn + p * 16 + b_rowoff) * 64 + csel;
                    LDSM_X4(bh[p*4+0], bh[p*4+1], bh[p*4+2], bh[p*4+3],
                            stb + OFF_B + ro);
                }
            }
            const uint32_t acsel = ((uint32_t)(ks * 2 + a_ksel) ^ a_swz) << 4;
#pragma unroll
            for (int mi = 0; mi < 4; mi++) {
                uint32_t ah[4], al[4];
                LDSM_X4(ah[0], ah[1], ah[2], ah[3], aBaseHi + mi * 16 * 64 + acsel);
                LDSM_X4(al[0], al[1], al[2], al[3], aBaseLo + mi * 16 * 64 + acsel);
#pragma unroll
                for (int ni = 0; ni < 4; ni++)
                    MMA_FP16(acc[mi][ni], ah, bh[ni*2], bh[ni*2+1]);
#pragma unroll
                for (int ni = 0; ni < 4; ni++)
                    MMA_FP16(acc[mi][ni], al, bh[ni*2], bh[ni*2+1]);
            }
        }
        __syncthreads();
    }

    // ---- epilogue ----
    const int erow = lane >> 2;
    const int ecol = (lane & 3) * 2;
#pragma unroll
    for (int mi = 0; mi < 4; mi++) {
        const int r0 = row0 + wm + mi * 16 + erow;
        const int r1 = r0 + 8;
#pragma unroll
        for (int ni = 0; ni < 4; ni++) {
            const int c = col0 + wn + ni * 8 + ecol;
            float v0 = acc[mi][ni][0], v1 = acc[mi][ni][1];
            float v2 = acc[mi][ni][2], v3 = acc[mi][ni][3];
            if (bias) {
                const float b0 = bias[c], b1 = bias[c + 1];
                v0 += b0; v1 += b1; v2 += b0; v3 += b1;
            }
            if (res) {
                float2 q0 = *(const float2*)(res + (long)r0 * ldc + c);
                float2 q1 = *(const float2*)(res + (long)r1 * ldc + c);
                v0 += q0.x; v1 += q0.y; v2 += q1.x; v3 += q1.y;
            }
            if (Ch && Cl) {
                __half h0, l0, h1, l1, h2, l2, h3, l3;
                split16(v0, h0, l0); split16(v1, h1, l1);
                split16(v2, h2, l2); split16(v3, h3, l3);
                *(uint32_t*)(Ch + cOff + (long)r0 * ldc + c) =
                    (uint32_t)__half_as_ushort(h0) | ((uint32_t)__half_as_ushort(h1) << 16);
                *(uint32_t*)(Cl + cOff + (long)r0 * ldc + c) =
                    (uint32_t)__half_as_ushort(l0) | ((uint32_t)__half_as_ushort(l1) << 16);
                *(uint32_t*)(Ch + cOff + (long)r1 * ldc + c) =
                    (uint32_t)__half_as_ushort(h2) | ((uint32_t)__half_as_ushort(h3) << 16);
                *(uint32_t*)(Cl + cOff + (long)r1 * ldc + c) =
                    (uint32_t)__half_as_ushort(l2) | ((uint32_t)__half_as_ushort(l3) << 16);
            } else if (Ch) {
                *(uint32_t*)(Ch + cOff + (long)r0 * ldc + c) = pack_h2(v0, v1);
                *(uint32_t*)(Ch + cOff + (long)r1 * ldc + c) = pack_h2(v2, v3);
            } else {
                float2 o0 = {v0, v1}, o1 = {v2, v3};
                *(float2*)(C + cOff + (long)r0 * ldc + c) = o0;
                *(float2*)(C + cOff + (long)r1 * ldc + c) = o1;
            }
        }
    }
}

// ---------------- softmax: fp32 scores -> fp16 pair attn ----------------
__global__ void __launch_bounds__(256)
softmax_kernel(const float* __restrict__ s, const void* __restrict__ mask,
               const float* __restrict__ vv,
               __half* __restrict__ ah, __half* __restrict__ al,
               int S, int H, float scale)
{
    const int i = blockIdx.x;
    const int z = blockIdx.y;
    const int b = z / H;
    const int h = z % H;
    const long base = ((long)z * S + (long)i) * S;
    const float* p = s + base;
    const float* vsp = vv + h * 8192 + b * 1024;
    const long mbase = (long)b * S * S + (long)i * S;
    const int tid = threadIdx.x;
    const int mode = g_mask_mode;

    bool mk[4];
    if (mode == 0) {
        const unsigned char* mp = (const unsigned char*)mask + mbase;
#pragma unroll
        for (int r = 0; r < 4; r++) mk[r] = mp[tid + r * 256] != 0;
    } else if (mode == 1) {
        const int* mp = (const int*)mask + mbase;
#pragma unroll
        for (int r = 0; r < 4; r++) mk[r] = mp[tid + r * 256] != 0;
    } else {
        const float* mp = (const float*)mask + mbase;
#pragma unroll
        for (int r = 0; r < 4; r++) mk[r] = mp[tid + r * 256] != 0.f;
    }

    float v[4];
    float mx = -3.4e38f;
#pragma unroll
    for (int r = 0; r < 4; r++) {
        const int j = tid + r * 256;
        float x = p[j] * scale + vsp[j];
        if (mk[r]) x = -1e9f;
        v[r] = x;
        mx = fmaxf(mx, x);
    }
    __shared__ float red[256];
    red[tid] = mx; __syncthreads();
    for (int st = 128; st > 0; st >>= 1) {
        if (tid < st) red[tid] = fmaxf(red[tid], red[tid + st]);
        __syncthreads();
    }
    mx = red[0]; __syncthreads();
    float sum = 0.f;
#pragma unroll
    for (int r = 0; r < 4; r++) { v[r] = __expf(v[r] - mx); sum += v[r]; }
    red[tid] = sum; __syncthreads();
    for (int st = 128; st > 0; st >>= 1) {
        if (tid < st) red[tid] += red[tid + st];
        __syncthreads();
    }
    const float inv = 1.f / red[0];
#pragma unroll
    for (int r = 0; r < 4; r++) {
        const long idx = base + tid + r * 256;
        __half h, l;
        split16(v[r] * inv, h, l);
        ah[idx] = h;
        al[idx] = l;
    }
}

// ---------------- LayerNorm over D=512 ----------------
__global__ void __launch_bounds__(256)
layernorm_kernel(const float* __restrict__ x, const float* __restrict__ gamma,
                 const float* __restrict__ beta, float* __restrict__ out, int D)
{
    const int row = blockIdx.x;
    const float* p = x + (long)row * D;
    const int tid = threadIdx.x;
    const float a0 = p[tid];
    const float a1 = p[tid + 256];
    __shared__ float red[256];
    red[tid] = a0 + a1; __syncthreads();
    for (int st = 128; st > 0; st >>= 1) {
        if (tid < st) red[tid] += red[tid + st];
        __syncthreads();
    }
    const float mean = red[0] / (float)D; __syncthreads();
    const float d0 = a0 - mean, d1 = a1 - mean;
    red[tid] = d0 * d0 + d1 * d1; __syncthreads();
    for (int st = 128; st > 0; st >>= 1) {
        if (tid < st) red[tid] += red[tid + st];
        __syncthreads();
    }
    const float rstd = rsqrtf(red[0] / (float)D + 1e-5f);
    out[(long)row * D + tid]       = d0 * rstd * gamma[tid] + beta[tid];
    out[(long)row * D + tid + 256] = d1 * rstd * gamma[tid + 256] + beta[tid + 256];
}

// ---------------- launch ----------------
extern "C" void kernel_launch(void* const* d_in, const int* in_sizes, int n_in,
                              void* d_out, int out_size)
{
    const float* Q     = (const float*)d_in[0];
    const float* Kin   = (const float*)d_in[1];
    const float* Vin   = (const float*)d_in[2];
    const void*  Mask  = d_in[3];
    const float* Wq    = (const float*)d_in[4];
    const float* bq    = (const float*)d_in[5];
    const float* Wk    = (const float*)d_in[6];
    const float* bv    = (const float*)d_in[9];
    const float* Wv    = (const float*)d_in[8];
    const float* Wo    = (const float*)d_in[10];
    const float* bo    = (const float*)d_in[11];
    const float* gamma = (const float*)d_in[12];
    const float* beta  = (const float*)d_in[13];
    float* out = (float*)d_out;

    __half *wkh,*wkl,*wqs,*qhh,*qll,*ksg,*wvs,*woth,*wotl,*vts,*mts,*qmh,*qml,*ah,*al,*cvh,*cvl,*nts;
    float *s,*o,*vv,*w2,*cpart,*crow;
    cudaGetSymbolAddress((void**)&wkh, g_wkh);  cudaGetSymbolAddress((void**)&wkl, g_wkl);
    cudaGetSymbolAddress((void**)&wqs, g_wqs);
    cudaGetSymbolAddress((void**)&qhh, g_qhh);  cudaGetSymbolAddress((void**)&qll, g_qll);
    cudaGetSymbolAddress((void**)&ksg, g_ksg);
    cudaGetSymbolAddress((void**)&wvs, g_wvs);
    cudaGetSymbolAddress((void**)&woth,g_woth); cudaGetSymbolAddress((void**)&wotl,g_wotl);
    cudaGetSymbolAddress((void**)&vts, g_vts);
    cudaGetSymbolAddress((void**)&mts, g_mts);
    cudaGetSymbolAddress((void**)&qmh, g_qmh);  cudaGetSymbolAddress((void**)&qml, g_qml);
    cudaGetSymbolAddress((void**)&ah,  g_ah);   cudaGetSymbolAddress((void**)&al,  g_al);
    cudaGetSymbolAddress((void**)&cvh, g_cvh);  cudaGetSymbolAddress((void**)&cvl, g_cvl);
    cudaGetSymbolAddress((void**)&nts, g_nts);
    cudaGetSymbolAddress((void**)&s,   g_s);
    cudaGetSymbolAddress((void**)&o,   g_o);
    cudaGetSymbolAddress((void**)&vv,  g_vv);
    cudaGetSymbolAddress((void**)&w2,  g_w2);
    cudaGetSymbolAddress((void**)&cpart, g_cpart);
    cudaGetSymbolAddress((void**)&crow,  g_crow);

    cudaFuncSetAttribute(tc_gemm3, cudaFuncAttributeMaxDynamicSharedMemorySize, GEMM_SMEM);

    const int S = 1024, H = 8;
    const long SS = (long)S * S;
    const long N4W = (long)512 * 8192 / 4;
    dim3 blk(256);

    // launches 0-4 (G1 lands at index 5 for ncu -s 5)
    detect_mask_kernel<<<1, 256>>>((const unsigned int*)Mask);
    split_pair_kernel<<<1024, blk>>>(Wk, wkh, wkl, N4W);
    round_kernel<<<1024, blk>>>(Wq, wqs, N4W);
    split_pair_kernel<<<1024, blk>>>(Q, qhh, qll, N4W);
    round_kernel<<<1024, blk>>>(Kin, ksg, N4W);

    // G1: mt[h][q][p] = sum_d Wk[q,hd]*Wq[p,hd]  -> single fp16
    tc_gemm3<<<dim3(4, 4, 8), blk, GEMM_SMEM>>>(wkh, wkl, wqs,
        nullptr, nullptr, nullptr, mts, nullptr,
        1024, 8192, 8192, 512,
        0, 1024, 0, 1024, 0, (long)512 * 512, 8);

    // G2: qm[h][i][q] = (Q @ M_h)[i,q] -> pair
    tc_gemm3<<<dim3(4, 64, 8), blk, GEMM_SMEM>>>(qhh, qll, mts,
        nullptr, nullptr, nullptr, qmh, qml,
        512, 512, 512, 512,
        0, 0, 0, (long)512 * 512, 0, (long)8192 * 512, 8);

    // G3: s (fp32) = qm @ K^T per (b,h)
    tc_gemm3<<<dim3(8, 8, 64), blk, GEMM_SMEM>>>(qmh, qml, ksg,
        nullptr, nullptr, s, nullptr, nullptr,
        512, 512, 512, 1024,
        (long)1024 * 512, (long)8192 * 512,
        (long)1024 * 512, 0,
        (long)H * SS, SS, 8);

    // helpers + remaining conversions
    w2_kernel<<<dim3(512, 8), blk>>>(Wk, bq, w2);
    vv_kernel<<<8192, blk>>>(Kin, w2, vv, 0.03125f);
    round_kernel<<<1024, blk>>>(Wv, wvs, N4W);
    transpose_pair_kernel<<<dim3(16, 256, 1), dim3(32, 8)>>>(Wo, woth, wotl,
                                                             8192, 512, 0, 0);
    transpose_single_kernel<<<dim3(16, 32, 8), dim3(32, 8)>>>(Vin, vts,
                                                              1024, 512, 524288, 524288);

    // softmax -> fp16 pair attn
    softmax_kernel<<<dim3(S, 64), blk>>>(s, Mask, vv, ah, al, S, H, 0.03125f);

    // G5: ctxv = attn @ vt^T -> pair
    tc_gemm3<<<dim3(4, 8, 64), blk, GEMM_SMEM>>>(ah, al, vts,
        nullptr, nullptr, nullptr, cvh, cvl,
        1024, 1024, 1024, 4096,
        (long)H * SS, SS,
        (long)512 * 1024, 0,
        (long)1024 * 4096, 512, 8);

    // G6: nt = wot @ Wv^T per h -> single fp16
    tc_gemm3<<<dim3(4, 4, 8), blk, GEMM_SMEM>>>(woth, wotl, wvs,
        nullptr, nullptr, nullptr, nts, nullptr,
        1024, 8192, 8192, 4096,
        0, 1024, 0, 1024, 0, 512, 8);

    // crow (needed only by G7)
    crowA_kernel<<<128, blk>>>(Wo, bv, cpart);
    crowB_kernel<<<1, 512>>>(cpart, bo, crow);

    // G7: o = ctxv @ nt^T + crow + Q (fp32 out)
    tc_gemm3<<<dim3(4, 64, 1), blk, GEMM_SMEM>>>(cvh, cvl, nts,
        crow, Q, o, nullptr, nullptr,
        4096, 4096, 4096, 512,
        0, 0, 0, 0, 0, 0, 1);

    // LayerNorm
    layernorm_kernel<<<8192, blk>>>(o, gamma, beta, out, 512);
}